// round 9
// baseline (speedup 1.0000x reference)
#include <cuda_runtime.h>
#include <cstdint>

#define NWARPS 4           // warps per block
#define PAIRS  4           // token pairs per warp tile
#define TOKPT  8           // tokens per warp tile
#define DIMK   32
#define NHEAD  4
#define NMAT   5           // Wv + 4*Wk
#define KT_STRIDE 33       // keyT row stride (scalar conflict-free)
#define QT_STRIDE 33       // qT row stride (scalar conflict-free)

struct __align__(16) Smem {
    float2 w2[NMAT][DIMK / 2][DIMK];       // 20480 B
    float  bias[NMAT][DIMK];               //   640 B
    float  g12p[NHEAD][36];                //   576 B (float4-readable rows)
    float  gate[NWARPS][32];               //   512 B [h*8 + t]
    float  keyT[NWARPS][32 * KT_STRIDE];   // 16896 B (also emb stage)
    float  qT[NWARPS][32 * QT_STRIDE];     // 16896 B
};                                         // total 56000 B + 1KB resv -> 4 CTAs/SM

__device__ __forceinline__ uint64_t pack2(float lo, float hi) {
    uint64_t r; asm("mov.b64 %0,{%1,%2};" : "=l"(r) : "f"(lo), "f"(hi)); return r;
}
__device__ __forceinline__ void unpack2(uint64_t v, float& a, float& b) {
    asm("mov.b64 {%0,%1},%2;" : "=f"(a), "=f"(b) : "l"(v));
}
__device__ __forceinline__ uint64_t ffma2(uint64_t a, uint64_t b, uint64_t c) {
    uint64_t d; asm("fma.rn.f32x2 %0,%1,%2,%3;" : "=l"(d) : "l"(a), "l"(b), "l"(c)); return d;
}
__device__ __forceinline__ uint64_t fmul2(uint64_t a, uint64_t b) {
    uint64_t d; asm("mul.rn.f32x2 %0,%1,%2;" : "=l"(d) : "l"(a), "l"(b)); return d;
}
__device__ __forceinline__ float rsqrt_a(float x){ float r; asm("rsqrt.approx.f32 %0,%1;" : "=f"(r) : "f"(x)); return r; }
__device__ __forceinline__ float sqrt_a (float x){ float r; asm("sqrt.approx.f32 %0,%1;"  : "=f"(r) : "f"(x)); return r; }
__device__ __forceinline__ float ex2_a  (float x){ float r; asm("ex2.approx.f32 %0,%1;"   : "=f"(r) : "f"(x)); return r; }
__device__ __forceinline__ float rcp_a  (float x){ float r; asm("rcp.approx.f32 %0,%1;"   : "=f"(r) : "f"(x)); return r; }

__global__ void __launch_bounds__(NWARPS * 32, 4)
engram_kernel(const float* __restrict__ emb,
              const float* __restrict__ hid,
              const float* __restrict__ Wv,
              const float* __restrict__ bv,
              const float* __restrict__ Wk,
              const float* __restrict__ bk,
              const float* __restrict__ g1,
              const float* __restrict__ g2,
              float* __restrict__ out,
              int ntiles)
{
    extern __shared__ char smem_raw[];
    Smem& s = *reinterpret_cast<Smem*>(smem_raw);

    const int tid  = threadIdx.x;
    const int lane = tid & 31;
    const int warp = tid >> 5;

    // ---- one-time setup ----
    for (int i = tid; i < NMAT * (DIMK / 2) * DIMK; i += blockDim.x) {
        int m   = i / ((DIMK / 2) * DIMK);
        int rem = i % ((DIMK / 2) * DIMK);
        int d2  = rem / DIMK;
        int k   = rem % DIMK;
        const float* W = (m == 0) ? Wv : (Wk + (size_t)(m - 1) * DIMK * DIMK);
        s.w2[m][d2][k] = make_float2(W[k * DIMK + 2 * d2], W[k * DIMK + 2 * d2 + 1]);
    }
    if (tid < DIMK) s.bias[0][tid] = bv[tid];
    for (int i = tid; i < NHEAD * DIMK; i += blockDim.x) {
        s.bias[1 + i / DIMK][i % DIMK] = bk[i];
        s.g12p[i / DIMK][i % DIMK] = g1[i] * g2[i];
    }
    __syncthreads();

    const float EPSF  = 1.1920929e-07f;
    const float INV32 = 0.03125f;
    const float ISQ32 = 0.17677669529663687f;   // 1/sqrt(32)
    const float LOG2E = 1.4426950408889634f;

    float*  kt   = s.keyT[warp];
    float*  qt   = s.qT[warp];
    float2* embs = reinterpret_cast<float2*>(kt);           // stage view (GEMV phase)
    const float4* emb4 = reinterpret_cast<const float4*>(kt);

    const int o  = lane >> 3;   // q staging: head of this lane's float4
    const int l8 = lane & 7;

    for (int tile = blockIdx.x * NWARPS + warp; tile < ntiles;
         tile += gridDim.x * NWARPS) {

        const int base = tile * TOKPT;

        // ---- stage emb pairs (4 pairs x 32 d) into keyT region ----
        const float* embp = emb + (size_t)base * DIMK;
#pragma unroll
        for (int p = 0; p < PAIRS; ++p) {
            float e0 = embp[(2 * p) * DIMK + lane];
            float e1 = embp[(2 * p + 1) * DIMK + lane];
            embs[p * DIMK + lane] = make_float2(e0, e1);
        }
        __syncwarp();

        // ---- accumulators: acc[mat][pair] packs 2 tokens, lane = k (40 regs) ----
        uint64_t acc[NMAT][PAIRS];
#pragma unroll
        for (int m = 0; m < NMAT; ++m) {
            float b = s.bias[m][lane];
            uint64_t b2 = pack2(b, b);
#pragma unroll
            for (int p = 0; p < PAIRS; ++p) acc[m][p] = b2;
        }

        // ---- GEMV ----
#pragma unroll 4
        for (int d2 = 0; d2 < DIMK / 2; ++d2) {
            uint64_t wa[NMAT], wb[NMAT];
#pragma unroll
            for (int m = 0; m < NMAT; ++m) {
                float2 w = s.w2[m][d2][lane];
                wa[m] = pack2(w.x, w.x);
                wb[m] = pack2(w.y, w.y);
            }
#pragma unroll
            for (int p = 0; p < PAIRS; ++p) {
                float4 e = emb4[p * (DIMK / 2) + d2];
                uint64_t ea = pack2(e.x, e.y);
                uint64_t eb = pack2(e.z, e.w);
#pragma unroll
                for (int m = 0; m < NMAT; ++m) {
                    acc[m][p] = ffma2(ea, wa[m], acc[m][p]);
                    acc[m][p] = ffma2(eb, wb[m], acc[m][p]);
                }
            }
        }
        __syncwarp();   // emb stage dead; region becomes keyT

        // ---- stage q: 8 coalesced LDG.128 -> qT rows (4t+o), conflict-free STS ----
        const float4* hid4 = reinterpret_cast<const float4*>(hid) + (size_t)base * 32;
#pragma unroll
        for (int t = 0; t < TOKPT; ++t) {
            float4 Q = hid4[t * 32 + lane];
            float* dst = qt + (4 * t + o) * QT_STRIDE + 4 * l8;
            dst[0] = Q.x; dst[1] = Q.y; dst[2] = Q.z; dst[3] = Q.w;
        }

        // ---- transpose keys: row c = 4t + h, stride 33, conflict-free scalar ----
#pragma unroll
        for (int h = 0; h < NHEAD; ++h)
#pragma unroll
            for (int p = 0; p < PAIRS; ++p) {
                float lo, hi; unpack2(acc[1 + h][p], lo, hi);
                kt[(8 * p + h)     * KT_STRIDE + lane] = lo;   // t = 2p
                kt[(8 * p + 4 + h) * KT_STRIDE + lane] = hi;   // t = 2p+1
            }
        __syncwarp();

        // ---- combo: lane owns c = 4t + h (exactly 32 combos) ----
        {
            const int h = lane & 3;
            const float* keyrow = kt + lane * KT_STRIDE;
            const float* qrow   = qt + lane * QT_STRIDE;
            const float4* grow  = reinterpret_cast<const float4*>(s.g12p[h]);

            float kss = 0.f, qss = 0.f, pdot = 0.f;
#pragma unroll
            for (int kk = 0; kk < 8; ++kk) {
                float4 g4 = grow[kk];          // LDS.128, octet broadcast
                float k0 = keyrow[4 * kk + 0];
                float k1 = keyrow[4 * kk + 1];
                float k2 = keyrow[4 * kk + 2];
                float k3 = keyrow[4 * kk + 3];
                float q0 = qrow[4 * kk + 0];
                float q1 = qrow[4 * kk + 1];
                float q2 = qrow[4 * kk + 2];
                float q3 = qrow[4 * kk + 3];
                kss  = fmaf(k0, k0, kss); qss = fmaf(q0, q0, qss);
                pdot = fmaf(k0 * q0, g4.x, pdot);
                kss  = fmaf(k1, k1, kss); qss = fmaf(q1, q1, qss);
                pdot = fmaf(k1 * q1, g4.y, pdot);
                kss  = fmaf(k2, k2, kss); qss = fmaf(q2, q2, qss);
                pdot = fmaf(k2 * q2, g4.z, pdot);
                kss  = fmaf(k3, k3, kss); qss = fmaf(q3, q3, qss);
                pdot = fmaf(k3 * q3, g4.w, pdot);
            }

            float rk = rsqrt_a(fmaf(kss, INV32, EPSF));
            float rq = rsqrt_a(fmaf(qss, INV32, EPSF));
            float gp = pdot * rk * rq * ISQ32;
            float a  = fmaxf(fabsf(gp), 1e-6f);
            float sr = copysignf(sqrt_a(a), gp);
            float ex = ex2_a(-sr * LOG2E);
            s.gate[warp][h * 8 + (lane >> 2)] = rcp_a(1.f + ex);
        }
        __syncwarp();

        // ---- output: out[tok][h][k] = gate * value ----
        float* outp = out + (size_t)base * (NHEAD * DIMK);
#pragma unroll
        for (int p = 0; p < PAIRS; ++p) {
#pragma unroll
            for (int h = 0; h < NHEAD; ++h) {
                uint64_t g2v = *reinterpret_cast<const uint64_t*>(
                    &s.gate[warp][h * 8 + 2 * p]);
                uint64_t ov = fmul2(g2v, acc[0][p]);
                float o0, o1; unpack2(ov, o0, o1);
                outp[(2 * p)     * (NHEAD * DIMK) + h * DIMK + lane] = o0;
                outp[(2 * p + 1) * (NHEAD * DIMK) + h * DIMK + lane] = o1;
            }
        }
        __syncwarp();
    }
}

extern "C" void kernel_launch(void* const* d_in, const int* in_sizes, int n_in,
                              void* d_out, int out_size)
{
    const float* emb = (const float*)d_in[0];
    const float* hid = (const float*)d_in[1];
    const float* Wv  = (const float*)d_in[2];
    const float* bv  = (const float*)d_in[3];
    const float* Wk  = (const float*)d_in[4];
    const float* bk  = (const float*)d_in[5];
    const float* g1  = (const float*)d_in[6];
    const float* g2  = (const float*)d_in[7];

    int ntok   = in_sizes[0] / DIMK;   // B*S
    int ntiles = ntok / TOKPT;         // 32768 for this shape

    size_t smem = sizeof(Smem);
    cudaFuncSetAttribute(engram_kernel,
                         cudaFuncAttributeMaxDynamicSharedMemorySize, (int)smem);

    int blocks = 2048;                 // 8192 warps -> 4 tiles per warp
    engram_kernel<<<blocks, NWARPS * 32, smem>>>(
        emb, hid, Wv, bv, Wk, bk, g1, g2, (float*)d_out, ntiles);
}

// round 10
// speedup vs baseline: 1.7042x; 1.7042x over previous
#include <cuda_runtime.h>
#include <cstdint>

#define NWARPS 4           // warps per block
#define PAIRS  8           // token pairs per warp tile
#define TOKPT  16          // tokens per warp tile
#define DIMK   32
#define NHEAD  4
#define NMAT   5           // Wv + 4*Wk
#define KT_STRIDE 33       // keyT row stride (scalar conflict-free)
#define QT_STRIDE 36       // qT row stride (16B-aligned, LDS.128 conflict-free)

struct __align__(16) Smem {
    float2 w2[NMAT][DIMK / 2][DIMK];      // 20480 B  (offset 0, 16B aligned)
    float  qT[NWARPS][64 * QT_STRIDE];    // 36864 B  (offset 20480, 16B aligned)
    float  keyT[NWARPS][32 * KT_STRIDE];  // 16896 B  (offset 57344; also emb stage)
    float  bias[NMAT][DIMK];              //   640 B
    float  g12p[NHEAD][KT_STRIDE];        //   528 B
    float  gate[NWARPS][64];              //  1024 B
};                                        // total 76432 B -> 3 CTAs/SM

__device__ __forceinline__ uint32_t smem_u32(const void* p) {
    uint32_t a; asm("{.reg .u64 t; cvta.to.shared.u64 t, %1; cvt.u32.u64 %0, t;}" : "=r"(a) : "l"(p));
    return a;
}
__device__ __forceinline__ void cp_async16(uint32_t dst, const void* src) {
    asm volatile("cp.async.cg.shared.global [%0], [%1], 16;" :: "r"(dst), "l"(src) : "memory");
}
#define CP_COMMIT() asm volatile("cp.async.commit_group;" ::: "memory")
#define CP_WAIT0()  asm volatile("cp.async.wait_group 0;" ::: "memory")

__device__ __forceinline__ uint64_t pack2(float lo, float hi) {
    uint64_t r; asm("mov.b64 %0,{%1,%2};" : "=l"(r) : "f"(lo), "f"(hi)); return r;
}
__device__ __forceinline__ void unpack2(uint64_t v, float& a, float& b) {
    asm("mov.b64 {%0,%1},%2;" : "=f"(a), "=f"(b) : "l"(v));
}
__device__ __forceinline__ uint64_t ffma2(uint64_t a, uint64_t b, uint64_t c) {
    uint64_t d; asm("fma.rn.f32x2 %0,%1,%2,%3;" : "=l"(d) : "l"(a), "l"(b), "l"(c)); return d;
}
__device__ __forceinline__ uint64_t fmul2(uint64_t a, uint64_t b) {
    uint64_t d; asm("mul.rn.f32x2 %0,%1,%2;" : "=l"(d) : "l"(a), "l"(b)); return d;
}
__device__ __forceinline__ float rsqrt_a(float x){ float r; asm("rsqrt.approx.f32 %0,%1;" : "=f"(r) : "f"(x)); return r; }
__device__ __forceinline__ float sqrt_a (float x){ float r; asm("sqrt.approx.f32 %0,%1;"  : "=f"(r) : "f"(x)); return r; }
__device__ __forceinline__ float ex2_a  (float x){ float r; asm("ex2.approx.f32 %0,%1;"   : "=f"(r) : "f"(x)); return r; }
__device__ __forceinline__ float rcp_a  (float x){ float r; asm("rcp.approx.f32 %0,%1;"   : "=f"(r) : "f"(x)); return r; }

__global__ void __launch_bounds__(NWARPS * 32, 3)
engram_kernel(const float* __restrict__ emb,
              const float* __restrict__ hid,
              const float* __restrict__ Wv,
              const float* __restrict__ bv,
              const float* __restrict__ Wk,
              const float* __restrict__ bk,
              const float* __restrict__ g1,
              const float* __restrict__ g2,
              float* __restrict__ out,
              int ntiles)
{
    extern __shared__ char smem_raw[];
    Smem& s = *reinterpret_cast<Smem*>(smem_raw);

    const int tid  = threadIdx.x;
    const int lane = tid & 31;
    const int warp = tid >> 5;

    // ---- one-time setup ----
    for (int i = tid; i < NMAT * (DIMK / 2) * DIMK; i += blockDim.x) {
        int m   = i / ((DIMK / 2) * DIMK);
        int rem = i % ((DIMK / 2) * DIMK);
        int d2  = rem / DIMK;
        int k   = rem % DIMK;
        const float* W = (m == 0) ? Wv : (Wk + (size_t)(m - 1) * DIMK * DIMK);
        s.w2[m][d2][k] = make_float2(W[k * DIMK + 2 * d2], W[k * DIMK + 2 * d2 + 1]);
    }
    if (tid < DIMK) s.bias[0][tid] = bv[tid];
    for (int i = tid; i < NHEAD * DIMK; i += blockDim.x) {
        s.bias[1 + i / DIMK][i % DIMK] = bk[i];
        s.g12p[i / DIMK][i % DIMK] = g1[i] * g2[i];
    }
    __syncthreads();

    const float EPSF  = 1.1920929e-07f;
    const float INV32 = 0.03125f;
    const float ISQ32 = 0.17677669529663687f;   // 1/sqrt(32)
    const float LOG2E = 1.4426950408889634f;

    float*  kt   = s.keyT[warp];
    float*  qt   = s.qT[warp];
    const uint32_t qt_u32 = smem_u32(qt);
    float2* embs = reinterpret_cast<float2*>(kt);           // stage view (GEMV phase)
    const float4* emb4 = reinterpret_cast<const float4*>(kt);

    const int o  = lane >> 3;   // q staging: head of this lane's 16B chunk
    const int l8 = lane & 7;

    for (int tile = blockIdx.x * NWARPS + warp; tile < ntiles;
         tile += gridDim.x * NWARPS) {

        const int base = tile * TOKPT;

        // ---- stage emb pairs into keyT region ----
        const float* embp = emb + (size_t)base * DIMK;
#pragma unroll
        for (int p = 0; p < PAIRS; ++p) {
            float e0 = embp[(2 * p) * DIMK + lane];
            float e1 = embp[(2 * p + 1) * DIMK + lane];
            embs[p * DIMK + lane] = make_float2(e0, e1);
        }

        // ---- q for BOTH rounds via cp.async (latency covered by GEMV) ----
        // row = 4t + o, stride 36 floats (dst 16B aligned), 16B per lane
        {
            const float* src0 = hid + ((size_t)base * 128 + (size_t)lane * 4);
#pragma unroll
            for (int t = 0; t < TOKPT; ++t) {
                uint32_t dst = qt_u32 + (((4 * t + o) * QT_STRIDE + 4 * l8) << 2);
                cp_async16(dst, src0 + (size_t)t * 128);
            }
            CP_COMMIT();
        }
        __syncwarp();

        // ---- accumulators: acc[mat][pair] packs 2 tokens, lane = k ----
        uint64_t acc[NMAT][PAIRS];
#pragma unroll
        for (int m = 0; m < NMAT; ++m) {
            float b = s.bias[m][lane];
            uint64_t b2 = pack2(b, b);
#pragma unroll
            for (int p = 0; p < PAIRS; ++p) acc[m][p] = b2;
        }

        // ---- GEMV ----
#pragma unroll 4
        for (int d2 = 0; d2 < DIMK / 2; ++d2) {
            uint64_t wa[NMAT], wb[NMAT];
#pragma unroll
            for (int m = 0; m < NMAT; ++m) {
                float2 w = s.w2[m][d2][lane];
                wa[m] = pack2(w.x, w.x);
                wb[m] = pack2(w.y, w.y);
            }
#pragma unroll
            for (int p = 0; p < PAIRS; ++p) {
                float4 e = emb4[p * (DIMK / 2) + d2];
                uint64_t ea = pack2(e.x, e.y);
                uint64_t eb = pack2(e.z, e.w);
#pragma unroll
                for (int m = 0; m < NMAT; ++m) {
                    acc[m][p] = ffma2(ea, wa[m], acc[m][p]);
                    acc[m][p] = ffma2(eb, wb[m], acc[m][p]);
                }
            }
        }
        CP_WAIT0();       // q ready (was issued ~GEMV-duration ago)
        __syncwarp();     // emb stage dead; keyT region free; qT visible warp-wide

        // ---- 2 rounds: per-round key transpose (32 rows) + combo ----
#pragma unroll
        for (int r = 0; r < 2; ++r) {
            // transpose pairs 4r..4r+3 -> rows 8*pl + h (+4 for odd token)
#pragma unroll
            for (int h = 0; h < NHEAD; ++h)
#pragma unroll
                for (int pl = 0; pl < 4; ++pl) {
                    float lo, hi; unpack2(acc[1 + h][4 * r + pl], lo, hi);
                    kt[(8 * pl + h)     * KT_STRIDE + lane] = lo;   // t_local = 2*pl
                    kt[(8 * pl + 4 + h) * KT_STRIDE + lane] = hi;   // t_local = 2*pl+1
                }
            __syncwarp();

            // lane owns combo: h = lane&3, t = 8r + (lane>>2)
            const int h = lane & 3;
            const float*  keyrow = kt + lane * KT_STRIDE;
            const float4* qrow4  = reinterpret_cast<const float4*>(
                qt + (32 * r + lane) * QT_STRIDE);
            const float*  grow   = s.g12p[h];

            float kss = 0.f, qss = 0.f, pdot = 0.f;
#pragma unroll
            for (int kk = 0; kk < 8; ++kk) {
                float4 q4 = qrow4[kk];                     // LDS.128 conflict-free
                float k0 = keyrow[4 * kk + 0];
                float k1 = keyrow[4 * kk + 1];
                float k2 = keyrow[4 * kk + 2];
                float k3 = keyrow[4 * kk + 3];
                float g0 = grow[4 * kk + 0];
                float g1v = grow[4 * kk + 1];
                float g2v = grow[4 * kk + 2];
                float g3 = grow[4 * kk + 3];
                kss  = fmaf(k0, k0, kss); qss = fmaf(q4.x, q4.x, qss);
                pdot = fmaf(k0 * q4.x, g0, pdot);
                kss  = fmaf(k1, k1, kss); qss = fmaf(q4.y, q4.y, qss);
                pdot = fmaf(k1 * q4.y, g1v, pdot);
                kss  = fmaf(k2, k2, kss); qss = fmaf(q4.z, q4.z, qss);
                pdot = fmaf(k2 * q4.z, g2v, pdot);
                kss  = fmaf(k3, k3, kss); qss = fmaf(q4.w, q4.w, qss);
                pdot = fmaf(k3 * q4.w, g3, pdot);
            }

            float rk = rsqrt_a(fmaf(kss, INV32, EPSF));
            float rq = rsqrt_a(fmaf(qss, INV32, EPSF));
            float gp = pdot * rk * rq * ISQ32;
            float a  = fmaxf(fabsf(gp), 1e-6f);
            float sr = copysignf(sqrt_a(a), gp);
            float ex = ex2_a(-sr * LOG2E);
            s.gate[warp][h * 16 + 8 * r + (lane >> 2)] = rcp_a(1.f + ex);
            __syncwarp();   // keyT reused next round / gates ready
        }

        // ---- output: out[tok][h][k] = gate * value ----
        float* outp = out + (size_t)base * (NHEAD * DIMK);
#pragma unroll
        for (int p = 0; p < PAIRS; ++p) {
#pragma unroll
            for (int h = 0; h < NHEAD; ++h) {
                uint64_t g2v = *reinterpret_cast<const uint64_t*>(
                    &s.gate[warp][h * 16 + 2 * p]);
                uint64_t ov = fmul2(g2v, acc[0][p]);
                float o0, o1; unpack2(ov, o0, o1);
                outp[(2 * p)     * (NHEAD * DIMK) + h * DIMK + lane] = o0;
                outp[(2 * p + 1) * (NHEAD * DIMK) + h * DIMK + lane] = o1;
            }
        }
        __syncwarp();   // protect gate/keyT/qT before next tile
    }
}

extern "C" void kernel_launch(void* const* d_in, const int* in_sizes, int n_in,
                              void* d_out, int out_size)
{
    const float* emb = (const float*)d_in[0];
    const float* hid = (const float*)d_in[1];
    const float* Wv  = (const float*)d_in[2];
    const float* bv  = (const float*)d_in[3];
    const float* Wk  = (const float*)d_in[4];
    const float* bk  = (const float*)d_in[5];
    const float* g1  = (const float*)d_in[6];
    const float* g2  = (const float*)d_in[7];

    int ntok   = in_sizes[0] / DIMK;   // B*S
    int ntiles = ntok / TOKPT;         // 16384 for this shape

    size_t smem = sizeof(Smem);
    cudaFuncSetAttribute(engram_kernel,
                         cudaFuncAttributeMaxDynamicSharedMemorySize, (int)smem);

    int blocks = 2048;                 // 8192 warps -> 2 tiles per warp
    engram_kernel<<<blocks, NWARPS * 32, smem>>>(
        emb, hid, Wv, bv, Wk, bk, g1, g2, (float*)d_out, ntiles);
}